// round 7
// baseline (speedup 1.0000x reference)
#include <cuda_runtime.h>
#include <math.h>

#define D_TOT 25088      // 512*7*7
#define B_SZ  16
#define N_TOT 2000
#define NS    9          // n-splits for pass 2 (441 blocks ~= 1 wave @3 CTA/SM)
#define NMAX  223        // max n per split
#define DQ    7          // d-segments for pass 1
#define CHK   128        // floats per pass-1 chunk
#define NCHK  28         // chunks per d-segment (7*28*128 = 25088)
#define STG   6          // pass-1 pipeline stages
#define KSEG  4          // knorm segments
#define PI2C  (3.14159f * 0.5f)

// ---- scratch ----
__device__ float g_kn2p[KSEG][B_SZ];                  // partial ||key||^2
__device__ float g_dotp[DQ][B_SZ][N_TOT];             // partial dots
__device__ float g_mn2p[DQ][N_TOT];                   // partial ||m_n||^2
__device__ unsigned long long g_wT2[N_TOT * B_SZ];    // weights, dup-packed [n][b]
__device__ float g_part[NS][B_SZ * D_TOT];            // pass-2 partials

// ---- packed fp32x2 helpers ----
__device__ __forceinline__ void ffma2(unsigned long long& acc,
                                      unsigned long long a, unsigned long long b) {
    asm("fma.rn.f32x2 %0, %1, %2, %0;" : "+l"(acc) : "l"(a), "l"(b));
}
__device__ __forceinline__ unsigned long long dup2(float v) {
    unsigned long long r;
    asm("mov.b64 %0, {%1, %1};" : "=l"(r) : "r"(__float_as_uint(v)));
    return r;
}
__device__ __forceinline__ float psum2(unsigned long long v) {
    float lo, hi;
    asm("mov.b64 {%0, %1}, %2;" : "=f"(lo), "=f"(hi) : "l"(v));
    return lo + hi;
}

// ================= kernel A: key norm partials =================
__global__ void k_knorm(const float* __restrict__ key) {
    const int b = blockIdx.x >> 2, seg = blockIdx.x & 3;
    const int len = D_TOT / 4 / KSEG;
    const float4* kp = reinterpret_cast<const float4*>(key + (size_t)b * D_TOT)
                       + seg * len;
    float s = 0.f;
    for (int i = threadIdx.x; i < len; i += blockDim.x) {
        float4 v = kp[i];
        s += v.x * v.x + v.y * v.y + v.z * v.z + v.w * v.w;
    }
    __shared__ float red[8];
    #pragma unroll
    for (int o = 16; o > 0; o >>= 1) s += __shfl_xor_sync(0xffffffffu, s, o);
    if ((threadIdx.x & 31) == 0) red[threadIdx.x >> 5] = s;
    __syncthreads();
    if (threadIdx.x == 0) {
        float t = 0.f;
        for (int w = 0; w < (int)(blockDim.x >> 5); w++) t += red[w];
        g_kn2p[seg][b] = t;
    }
}

// ================= kernel B: dots + memory norms (pass 1) =================
// grid (125, 7). 256 threads = 8 warps: q=wi&3 -> 4 b; g=wi>>2 -> 8 n.
// 6-stage cp.async ring; ONE wait+sync per TWO chunks; k reg-prefetch.
__global__ void __launch_bounds__(256, 2) k_pass1(const float* __restrict__ key,
                                                  const float* __restrict__ mem) {
    __shared__ __align__(16) float sm[STG][16 * CHK];   // 48KB
    const int tid = threadIdx.x;
    const int wi = tid >> 5, ln = tid & 31;
    const int q = wi & 3, g = wi >> 2;
    const int b0 = q * 4, ng = g * 8;
    const int nb = blockIdx.x * 16;
    const int dq = blockIdx.y;
    const int dbase = dq * (NCHK * CHK);
    const int col = ln << 2;

    auto stage = [&](int c) {
        const int d0 = dbase + c * CHK;
        float* buf = sm[c % STG];
        #pragma unroll
        for (int k2i = 0; k2i < 2; k2i++) {
            int fidx = tid + (k2i << 8);
            int nn = fidx >> 5, c4 = fidx & 31;
            const float* src = mem + (size_t)(nb + nn) * D_TOT + d0 + (c4 << 2);
            unsigned dst = (unsigned)__cvta_generic_to_shared(&buf[nn * CHK + (c4 << 2)]);
            asm volatile("cp.async.cg.shared.global [%0], [%1], 16;" ::
                         "r"(dst), "l"(src));
        }
        asm volatile("cp.async.commit_group;" ::: "memory");
    };

    #pragma unroll
    for (int c = 0; c < 4; c++) stage(c);

    unsigned long long acc[4][8];
    #pragma unroll
    for (int i = 0; i < 4; i++)
        #pragma unroll
        for (int j = 0; j < 8; j++) acc[i][j] = 0ull;
    unsigned long long na0 = 0ull, na1 = 0ull;

    // k prefetch: registers hold chunk c's keys, loaded during chunk c-1
    ulonglong2 k2[4];
    #pragma unroll
    for (int bb = 0; bb < 4; bb++)
        k2[bb] = *reinterpret_cast<const ulonglong2*>(
            key + (size_t)(b0 + bb) * D_TOT + dbase + col);

    auto compute_chunk = [&](int c) {
        const float* smc = sm[c % STG];
        const int cn = (c + 1 < NCHK) ? c + 1 : c;
        const int dgn = dbase + cn * CHK + col;
        ulonglong2 k2n[4];
        #pragma unroll
        for (int bb = 0; bb < 4; bb++)
            k2n[bb] = *reinterpret_cast<const ulonglong2*>(
                key + (size_t)(b0 + bb) * D_TOT + dgn);

        #pragma unroll
        for (int nn = 0; nn < 8; nn++) {
            ulonglong2 m = *reinterpret_cast<const ulonglong2*>(
                smc + (ng + nn) * CHK + col);
            #pragma unroll
            for (int bb = 0; bb < 4; bb++) {
                ffma2(acc[bb][nn], m.x, k2[bb].x);
                ffma2(acc[bb][nn], m.y, k2[bb].y);
            }
            if (nn == 2 * q)     { ffma2(na0, m.x, m.x); ffma2(na0, m.y, m.y); }
            if (nn == 2 * q + 1) { ffma2(na1, m.x, m.x); ffma2(na1, m.y, m.y); }
        }
        #pragma unroll
        for (int bb = 0; bb < 4; bb++) k2[bb] = k2n[bb];
    };

    for (int p = 0; p < NCHK / 2; p++) {
        const int c0 = 2 * p;
        asm volatile("cp.async.wait_group 2;" ::: "memory");
        __syncthreads();
        if (c0 + 4 < NCHK) stage(c0 + 4);
        if (c0 + 5 < NCHK) stage(c0 + 5);
        compute_chunk(c0);
        compute_chunk(c0 + 1);
    }

    #pragma unroll
    for (int bb = 0; bb < 4; bb++) {
        #pragma unroll
        for (int nn = 0; nn < 8; nn++) {
            float v = psum2(acc[bb][nn]);
            #pragma unroll
            for (int o = 16; o > 0; o >>= 1) v += __shfl_xor_sync(0xffffffffu, v, o);
            if (ln == 0) g_dotp[dq][b0 + bb][nb + ng + nn] = v;
        }
    }
    {
        float v0 = psum2(na0), v1 = psum2(na1);
        #pragma unroll
        for (int o = 16; o > 0; o >>= 1) {
            v0 += __shfl_xor_sync(0xffffffffu, v0, o);
            v1 += __shfl_xor_sync(0xffffffffu, v1, o);
        }
        if (ln == 0) {
            g_mn2p[dq][nb + ng + 2 * q]     = v0;
            g_mn2p[dq][nb + ng + 2 * q + 1] = v1;
        }
    }
}

// ================= kernel C: softmax of tan(cos * PI/2) =================
__global__ void k_softmax() {
    const int b = blockIdx.x;
    __shared__ float lg[N_TOT];
    __shared__ float red[32];
    const int tid = threadIdx.x;

    float kn2 = 0.f;
    #pragma unroll
    for (int s = 0; s < KSEG; s++) kn2 += g_kn2p[s][b];
    const float knr = sqrtf(kn2);

    float mx = -1e30f;
    for (int n = tid; n < N_TOT; n += blockDim.x) {
        float dot = 0.f, mn2 = 0.f;
        #pragma unroll
        for (int dq = 0; dq < DQ; dq++) {
            dot += g_dotp[dq][b][n];
            mn2 += g_mn2p[dq][n];
        }
        float cs = dot / (knr * sqrtf(mn2));
        float l = tanf(cs * PI2C);
        lg[n] = l;
        mx = fmaxf(mx, l);
    }
    #pragma unroll
    for (int o = 16; o > 0; o >>= 1) mx = fmaxf(mx, __shfl_xor_sync(0xffffffffu, mx, o));
    if ((tid & 31) == 0) red[tid >> 5] = mx;
    __syncthreads();
    if (tid == 0) {
        float t = -1e30f;
        for (int w = 0; w < (int)(blockDim.x >> 5); w++) t = fmaxf(t, red[w]);
        red[0] = t;
    }
    __syncthreads();
    mx = red[0];
    __syncthreads();

    float s = 0.f;
    for (int n = tid; n < N_TOT; n += blockDim.x) {
        float e = expf(lg[n] - mx);
        lg[n] = e;
        s += e;
    }
    #pragma unroll
    for (int o = 16; o > 0; o >>= 1) s += __shfl_xor_sync(0xffffffffu, s, o);
    if ((tid & 31) == 0) red[tid >> 5] = s;
    __syncthreads();
    if (tid == 0) {
        float t = 0.f;
        for (int w = 0; w < (int)(blockDim.x >> 5); w++) t += red[w];
        red[0] = t;
    }
    __syncthreads();
    const float inv = 1.f / red[0];
    for (int n = tid; n < N_TOT; n += blockDim.x)
        g_wT2[(size_t)n * B_SZ + b] = dup2(lg[n] * inv);
}

// ================= kernel D: weighted read (pass 2) =================
// grid (49, NS=9), 256 threads, 3 CTA/SM. B split across block halves:
// tid>>7 selects b range [8h, 8h+8). 16 u64 acc/thread; distance-4 prefetch.
__global__ void __launch_bounds__(256, 3) k_read(const float* __restrict__ mem) {
    const int db = blockIdx.x, ns = blockIdx.y;
    const int n0  = ns * 222 + min(ns, 2);
    const int len = 222 + (ns < 2 ? 1 : 0);           // 223 x2, 222 x7 = 2000
    const int tid = threadIdx.x;
    const int lane_d = tid & 127, half = tid >> 7;
    const int d = db * 512 + lane_d * 4;

    __shared__ __align__(16) ulonglong2 sw2[NMAX * (B_SZ / 2)];  // [n][8 pairs]
    {
        const ulonglong2* src = reinterpret_cast<const ulonglong2*>(
            g_wT2 + (size_t)n0 * B_SZ);
        for (int i = tid; i < len * (B_SZ / 2); i += blockDim.x) sw2[i] = src[i];
    }
    __syncthreads();

    unsigned long long acc[16];   // 8 b x 2 d-pairs
    #pragma unroll
    for (int i = 0; i < 16; i++) acc[i] = 0ull;

    const float* mp = mem + (size_t)n0 * D_TOT + d;
    const int nfull = (len >> 2) << 2;

    ulonglong2 mr[4];
    #pragma unroll
    for (int j = 0; j < 4; j++)
        mr[j] = *reinterpret_cast<const ulonglong2*>(mp + (size_t)j * D_TOT);

    for (int nb4 = 0; nb4 < nfull; nb4 += 4) {
        #pragma unroll
        for (int j = 0; j < 4; j++) {
            int pf = nb4 + 4 + j; if (pf >= len) pf = len - 1;
            ulonglong2 nx = *reinterpret_cast<const ulonglong2*>(
                mp + (size_t)pf * D_TOT);
            const ulonglong2* wp = sw2 + (nb4 + j) * (B_SZ / 2) + half * 4;
            #pragma unroll
            for (int p = 0; p < 4; p++) {
                ulonglong2 wv = wp[p];                 // weights b=8h+2p, 8h+2p+1
                ffma2(acc[4 * p],     wv.x, mr[j].x);
                ffma2(acc[4 * p + 1], wv.x, mr[j].y);
                ffma2(acc[4 * p + 2], wv.y, mr[j].x);
                ffma2(acc[4 * p + 3], wv.y, mr[j].y);
            }
            mr[j] = nx;
        }
    }
    // tail (len % 4 = 2 or 3): data already in mr via clamped prefetch
    for (int n = nfull; n < len; n++) {
        ulonglong2 m = mr[n - nfull];
        const ulonglong2* wp = sw2 + n * (B_SZ / 2) + half * 4;
        #pragma unroll
        for (int p = 0; p < 4; p++) {
            ulonglong2 wv = wp[p];
            ffma2(acc[4 * p],     wv.x, m.x);
            ffma2(acc[4 * p + 1], wv.x, m.y);
            ffma2(acc[4 * p + 2], wv.y, m.x);
            ffma2(acc[4 * p + 3], wv.y, m.y);
        }
    }

    float* pp = g_part[ns];
    #pragma unroll
    for (int p = 0; p < 4; p++) {
        const int b0 = half * 8 + 2 * p;
        ulonglong2 v0; v0.x = acc[4 * p];     v0.y = acc[4 * p + 1];
        ulonglong2 v1; v1.x = acc[4 * p + 2]; v1.y = acc[4 * p + 3];
        *reinterpret_cast<ulonglong2*>(pp + (size_t)b0       * D_TOT + d) = v0;
        *reinterpret_cast<ulonglong2*>(pp + (size_t)(b0 + 1) * D_TOT + d) = v1;
    }
}

// ================= kernel E: sum partials =================
__global__ void k_final(float* __restrict__ out) {
    const int i = blockIdx.x * blockDim.x + threadIdx.x;  // float4 index
    float4 s = make_float4(0.f, 0.f, 0.f, 0.f);
    #pragma unroll
    for (int p = 0; p < NS; p++) {
        float4 v = reinterpret_cast<const float4*>(g_part[p])[i];
        s.x += v.x; s.y += v.y; s.z += v.z; s.w += v.w;
    }
    reinterpret_cast<float4*>(out)[i] = s;
}

// ================= launcher =================
extern "C" void kernel_launch(void* const* d_in, const int* in_sizes, int n_in,
                              void* d_out, int out_size) {
    const float* key = (const float*)d_in[0];
    const float* mem = (const float*)d_in[1];
    if (n_in >= 2 && in_sizes[0] > in_sizes[1]) {
        const float* t = key; key = mem; mem = t;
    }
    k_knorm<<<B_SZ * KSEG, 256>>>(key);
    k_pass1<<<dim3(N_TOT / 16, DQ), 256>>>(key, mem);
    k_softmax<<<B_SZ, 256>>>();
    k_read<<<dim3(D_TOT / 512, NS), 256>>>(mem);
    k_final<<<(B_SZ * D_TOT / 4) / 256, 256>>>((float*)d_out);
}